// round 13
// baseline (speedup 1.0000x reference)
#include <cuda_runtime.h>
#include <cuda_bf16.h>
#include <math.h>
#include <stdint.h>

// Model dims: B=64,T=512,F=161,V=32,L=64,H=128,E=32
// conv1: (64,1,512,161)->(64,32,241,80)  conv2: ->(64,32,105,36) -> (64,105,1152)
#define NB 64
#define C1H 241
#define C1W 80
#define C2H 105

typedef unsigned long long ull;

// ---------------- device scratch ----------------
// conv1 output as bf16 hi/lo, layout [b][ih][iw][ci]
__device__ __nv_bfloat16 g_c1h[NB * C1H * C1W * 32];
__device__ __nv_bfloat16 g_c1l[NB * C1H * C1W * 32];
__device__ float g_conv2[NB * C2H * 1152];
__device__ float g_xp   [NB * C2H * 384];
__device__ float g_eh   [NB * C2H * 128];
__device__ float g_embA [NB * 63 * 32];
__device__ float g_ip   [NB * 63 * 384];
__device__ float g_ctxs [NB * 63 * 128];
__device__ float g_wT   [128 * 384];
// conv2 weight B-fragments pre-packed per mma lane:
// index (((kh*9+kw)*2+kc)*2+np)*32+lane -> uint4 = (b0,b1) for co-tiles (lo8, hi8)
__device__ uint4 g_wfh[36864];
__device__ uint4 g_wfl[36864];

// ---------------- helpers ----------------
__device__ __forceinline__ uint32_t smem_u32(const void* p) {
    uint32_t a;
    asm("{ .reg .u64 t; cvta.to.shared.u64 t, %1; cvt.u32.u64 %0, t; }" : "=r"(a) : "l"(p));
    return a;
}
__device__ __forceinline__ void ldsm4(uint32_t* d, uint32_t addr) {
    asm volatile("ldmatrix.sync.aligned.m8n8.x4.shared.b16 {%0,%1,%2,%3}, [%4];"
                 : "=r"(d[0]), "=r"(d[1]), "=r"(d[2]), "=r"(d[3]) : "r"(addr));
}
__device__ __forceinline__ void mma_bf16(float* c, const uint32_t* a,
                                         uint32_t b0, uint32_t b1) {
    asm volatile(
        "mma.sync.aligned.m16n8k16.row.col.f32.bf16.bf16.f32 "
        "{%0,%1,%2,%3}, {%4,%5,%6,%7}, {%8,%9}, {%0,%1,%2,%3};"
        : "+f"(c[0]), "+f"(c[1]), "+f"(c[2]), "+f"(c[3])
        : "r"(a[0]), "r"(a[1]), "r"(a[2]), "r"(a[3]), "r"(b0), "r"(b1));
}
__device__ __forceinline__ void cpa16(uint32_t dst, const void* src) {
    asm volatile("cp.async.cg.shared.global [%0], [%1], 16;" :: "r"(dst), "l"(src));
}
__device__ __forceinline__ uint32_t pack_bf2(float x, float y) {
    __nv_bfloat16 h0 = __float2bfloat16(x), h1 = __float2bfloat16(y);
    return ((uint32_t)__bfloat16_as_ushort(h1) << 16) | (uint32_t)__bfloat16_as_ushort(h0);
}

// ---------------- conv1: normalize + conv + relu -> bf16 hi/lo [ih][iw][ci] ----
__global__ void conv1_kernel(const float* __restrict__ x,
                             const float* __restrict__ mean,
                             const float* __restrict__ stdv,
                             const float* __restrict__ w,
                             const float* __restrict__ bias) {
    int oh = blockIdx.x, b = blockIdx.y;
    __shared__ float s_x[32 * 161];
    __shared__ float s_w[2048];
    __shared__ __nv_bfloat16 s_oh[2560], s_ol[2560];
    int tid = threadIdx.x;
    for (int i = tid; i < 32 * 161; i += 256) {
        int kh = i / 161, iw = i % 161;
        int ih = 2 * oh + kh;
        s_x[i] = (x[(b * 512 + ih) * 161 + iw] - mean[iw]) / stdv[iw];
    }
    for (int i = tid; i < 2048; i += 256) s_w[i] = w[i];
    __syncthreads();

    int c = tid >> 3, owb = tid & 7;
    float acc[10];
#pragma unroll
    for (int j = 0; j < 10; j++) acc[j] = 0.f;
    for (int kh = 0; kh < 32; kh++) {
        float w0 = s_w[c * 64 + kh * 2], w1 = s_w[c * 64 + kh * 2 + 1];
        const float* xr = &s_x[kh * 161];
#pragma unroll
        for (int j = 0; j < 10; j++) {
            int ow = owb + 8 * j;
            acc[j] += w0 * xr[2 * ow] + w1 * xr[2 * ow + 1];
        }
    }
    float bb = bias[c];
#pragma unroll
    for (int j = 0; j < 10; j++) {
        int ow = owb + 8 * j;
        float v = acc[j] + bb;
        v = v > 0.f ? v : 0.f;
        __nv_bfloat16 h = __float2bfloat16(v);
        s_oh[ow * 32 + c] = h;
        s_ol[ow * 32 + c] = __float2bfloat16(v - __bfloat162float(h));
    }
    __syncthreads();
    size_t base = (size_t)(b * C1H + oh) * 2560;
    const uint4* sh = (const uint4*)s_oh;
    const uint4* sl = (const uint4*)s_ol;
    uint4* dh = (uint4*)&g_c1h[base];
    uint4* dl = (uint4*)&g_c1l[base];
    for (int i = tid; i < 320; i += 256) { dh[i] = sh[i]; dl[i] = sl[i]; }
}

// -------- prep conv2 weight B-fragments (hi/lo), one uint4 pair per thread -----
__global__ void prep_wf(const float* __restrict__ w) {
    int i = blockIdx.x * 256 + threadIdx.x;
    if (i >= 36864) return;
    int lane = i & 31; int t = i >> 5;
    int np = t & 1; t >>= 1;
    int kc = t & 1; t >>= 1;
    int kw = t % 9; int kh = t / 9;
    int co0 = np * 16 + (lane >> 2);
    int ci0 = kc * 16 + 2 * (lane & 3);
    uint32_t rh[4], rl[4];
#pragma unroll
    for (int j = 0; j < 4; j++) {
        int co = co0 + (j >> 1) * 8;
        int ci = ci0 + (j & 1) * 8;
        float v0 = w[((co * 32 + ci) * 32 + kh) * 9 + kw];
        float v1 = w[((co * 32 + ci + 1) * 32 + kh) * 9 + kw];
        __nv_bfloat16 h0 = __float2bfloat16(v0), h1 = __float2bfloat16(v1);
        rh[j] = ((uint32_t)__bfloat16_as_ushort(h1) << 16)
              | (uint32_t)__bfloat16_as_ushort(h0);
        rl[j] = pack_bf2(v0 - __bfloat162float(h0), v1 - __bfloat162float(h1));
    }
    g_wfh[i] = make_uint4(rh[0], rh[1], rh[2], rh[3]);
    g_wfl[i] = make_uint4(rl[0], rl[1], rl[2], rl[3]);
}

// ---------------- conv2 via mma.sync: shifted-window, 2 M-tiles per warp -------
// grid (15, 64), 384 threads. CTA = (b, 7 oh rows => 252 pos, M=256 pad), N=32.
// A double-buffered (89600B each); B fragments direct from L2, amortized over
// 2 row-tiles per warp (warp w owns tiles w and w+8).
__global__ void __launch_bounds__(384) conv2_mma_kernel(const float* __restrict__ bias) {
    extern __shared__ __align__(16) char base[];
    uint32_t sb = smem_u32(base);
    int tid = threadIdx.x, wid = tid >> 5, lane = tid & 31;
    int oh0 = blockIdx.x * 7, b = blockIdx.y;
    const __nv_bfloat16* c1h = g_c1h + (size_t)b * C1H * 2560;
    const __nv_bfloat16* c1l = g_c1l + (size_t)b * C1H * 2560;

    float acc[2][4][4];
#pragma unroll
    for (int u = 0; u < 2; u++)
#pragma unroll
        for (int i = 0; i < 4; i++)
#pragma unroll
            for (int j = 0; j < 4; j++) acc[u][i][j] = 0.f;

    int r = lane & 7, q = lane >> 3;
    uint32_t a_base[2];
#pragma unroll
    for (int u = 0; u < 2; u++) {
        int p = 16 * (wid + 8 * u) + (q & 1) * 8 + r;
        if (p > 251) p = 251;
        int pohi = p / 36, pow_ = p - 36 * pohi;
        a_base[u] = (uint32_t)((pohi * 80 + 2 * pow_) * 80) + (q >> 1) * 16;
    }

    // ---- stage A rows (7 oh -> 560 iw-rows x 32 ci, hi+lo) for one kh ----
    auto stage = [&](int kh, int buf) {
        uint32_t xh = sb + (uint32_t)buf * 89600u;
        uint32_t xl = xh + 44800u;
        int ihb = 2 * oh0 + kh;
        for (int i = tid; i < 2240; i += 384) {
            int R = i >> 2, c8 = i & 3;
            int ohi2 = R / 80, iw = R - 80 * ohi2;
            size_t src = ((size_t)(ihb + 2 * ohi2) * 80 + iw) * 32 + c8 * 8;
            uint32_t d = (uint32_t)(R * 80 + c8 * 16);
            cpa16(xh + d, c1h + src);
            cpa16(xl + d, c1l + src);
        }
        asm volatile("cp.async.commit_group;" ::: "memory");
    };

    stage(0, 0);
    for (int kh = 0; kh < 32; kh++) {
        if (kh < 31) {
            stage(kh + 1, (kh + 1) & 1);
            asm volatile("cp.async.wait_group 1;" ::: "memory");
        } else {
            asm volatile("cp.async.wait_group 0;" ::: "memory");
        }
        __syncthreads();

        if (wid < 8) {
            uint32_t xh = sb + (uint32_t)(kh & 1) * 89600u;
            uint32_t xl = xh + 44800u;
            const uint4* wfh = g_wfh + (size_t)kh * 1152 + lane;
            const uint4* wfl = g_wfl + (size_t)kh * 1152 + lane;
#pragma unroll 3
            for (int kw = 0; kw < 9; kw++) {
#pragma unroll
                for (int kc = 0; kc < 2; kc++) {
                    uint32_t ah[2][4], al[2][4];
#pragma unroll
                    for (int u = 0; u < 2; u++) {
                        uint32_t akw = a_base[u] + (uint32_t)kw * 80 + kc * 32;
                        ldsm4(ah[u], xh + akw);
                        ldsm4(al[u], xl + akw);
                    }
#pragma unroll
                    for (int np = 0; np < 2; np++) {
                        int fi = ((kw * 2 + kc) * 2 + np) * 32;
                        uint4 bh = wfh[fi];
                        uint4 bl = wfl[fi];
#pragma unroll
                        for (int u = 0; u < 2; u++) {
                            mma_bf16(acc[u][2 * np],     ah[u], bh.x, bh.y);
                            mma_bf16(acc[u][2 * np + 1], ah[u], bh.z, bh.w);
                            mma_bf16(acc[u][2 * np],     ah[u], bl.x, bl.y);
                            mma_bf16(acc[u][2 * np + 1], ah[u], bl.z, bl.w);
                            mma_bf16(acc[u][2 * np],     al[u], bh.x, bh.y);
                            mma_bf16(acc[u][2 * np + 1], al[u], bh.z, bh.w);
                        }
                    }
                }
            }
        }
        __syncthreads();
    }

    // epilogue: fragments -> g_conv2 (b, t, co*36+ow), +bias, relu
    if (wid < 8) {
#pragma unroll
        for (int u = 0; u < 2; u++) {
            int row0 = 16 * (wid + 8 * u) + (lane >> 2);
#pragma unroll
            for (int nt = 0; nt < 4; nt++) {
                int col = 8 * nt + (lane & 3) * 2;
                float b0 = bias[col], b1 = bias[col + 1];
#pragma unroll
                for (int h = 0; h < 2; h++) {
                    int row = row0 + 8 * h;
                    if (row < 252) {
                        int ohi = row / 36, ow = row - 36 * ohi;
                        float* dst = &g_conv2[((size_t)b * C2H + oh0 + ohi) * 1152 + ow];
                        float v0 = acc[u][nt][2 * h] + b0;
                        float v1 = acc[u][nt][2 * h + 1] + b1;
                        dst[col * 36] = v0 > 0.f ? v0 : 0.f;
                        dst[(col + 1) * 36] = v1 > 0.f ? v1 : 0.f;
                    }
                }
            }
        }
    }
}

// ---------------- generic C[M,N] = A[M,K] * B[N,K]^T + bias ----------------
__global__ void gemm_nt(const float* __restrict__ A, const float* __restrict__ Bm,
                        const float* __restrict__ bias, float* __restrict__ C,
                        int M, int N, int K) {
    __shared__ float sA[8][128];
    __shared__ float sB[8][128];
    int bm = blockIdx.y * 128, bn = blockIdx.x * 128;
    int tid = threadIdx.x;
    int ty = tid >> 4, tx = tid & 15;
    float acc[8][8];
#pragma unroll
    for (int i = 0; i < 8; i++)
#pragma unroll
        for (int j = 0; j < 8; j++) acc[i][j] = 0.f;

    int lrow = tid >> 1, lk = (tid & 1) * 4;
    for (int k0 = 0; k0 < K; k0 += 8) {
        float4 av = make_float4(0.f, 0.f, 0.f, 0.f);
        float4 bv = make_float4(0.f, 0.f, 0.f, 0.f);
        if (bm + lrow < M) av = *(const float4*)&A[(size_t)(bm + lrow) * K + k0 + lk];
        if (bn + lrow < N) bv = *(const float4*)&Bm[(size_t)(bn + lrow) * K + k0 + lk];
        sA[lk + 0][lrow] = av.x; sA[lk + 1][lrow] = av.y;
        sA[lk + 2][lrow] = av.z; sA[lk + 3][lrow] = av.w;
        sB[lk + 0][lrow] = bv.x; sB[lk + 1][lrow] = bv.y;
        sB[lk + 2][lrow] = bv.z; sB[lk + 3][lrow] = bv.w;
        __syncthreads();
#pragma unroll
        for (int k = 0; k < 8; k++) {
            float a[8], bb[8];
            *(float4*)&a[0] = *(const float4*)&sA[k][ty * 8];
            *(float4*)&a[4] = *(const float4*)&sA[k][ty * 8 + 4];
            *(float4*)&bb[0] = *(const float4*)&sB[k][tx * 8];
            *(float4*)&bb[4] = *(const float4*)&sB[k][tx * 8 + 4];
#pragma unroll
            for (int i = 0; i < 8; i++)
#pragma unroll
                for (int j = 0; j < 8; j++) acc[i][j] += a[i] * bb[j];
        }
        __syncthreads();
    }
    for (int i = 0; i < 8; i++) {
        int m = bm + ty * 8 + i;
        if (m >= M) break;
        for (int j = 0; j < 8; j++) {
            int n = bn + tx * 8 + j;
            if (n < N) C[(size_t)m * N + n] = acc[i][j] + bias[n];
        }
    }
}

// ---------------- encoder GRU: one block per batch element ----------------
__global__ void encoder_kernel(const float* __restrict__ w_hh,
                               const float* __restrict__ b_hh) {
    extern __shared__ float sm[];
    float* s_w = sm;              // 384*132 (padded stride)
    float* s_h = sm + 50688;
    float* s_gh = sm + 50816;
    int b = blockIdx.x, tid = threadIdx.x;
    for (int i = tid; i < 49152; i += 384) {
        int r = i >> 7, c = i & 127;
        s_w[r * 132 + c] = w_hh[i];
    }
    if (tid < 128) s_h[tid] = 0.f;
    __syncthreads();
    float bn = b_hh[tid];
    const float4* wr = (const float4*)&s_w[tid * 132];
    for (int t = 0; t < 105; t++) {
        float a0 = bn, a1 = 0.f;
#pragma unroll
        for (int k = 0; k < 16; k++) {
            float4 wv = wr[2 * k];
            float4 hv = ((const float4*)s_h)[2 * k];
            a0 += wv.x * hv.x + wv.y * hv.y + wv.z * hv.z + wv.w * hv.w;
            float4 wv2 = wr[2 * k + 1];
            float4 hv2 = ((const float4*)s_h)[2 * k + 1];
            a1 += wv2.x * hv2.x + wv2.y * hv2.y + wv2.z * hv2.z + wv2.w * hv2.w;
        }
        s_gh[tid] = a0 + a1;
        __syncthreads();
        if (tid < 128) {
            const float* xrow = &g_xp[((size_t)b * 105 + t) * 384];
            float r = 1.f / (1.f + __expf(-(xrow[tid] + s_gh[tid])));
            float z = 1.f / (1.f + __expf(-(xrow[128 + tid] + s_gh[128 + tid])));
            float nn = tanhf(xrow[256 + tid] + r * s_gh[256 + tid]);
            float hnew = (1.f - z) * nn + z * s_h[tid];
            s_h[tid] = hnew;
            g_eh[((size_t)b * 105 + t) * 128 + tid] = hnew;
        }
        __syncthreads();
    }
}

// ---------------- decoder: GRU step + attention, one block per batch ----------------
__device__ __forceinline__ float warpred_max(float v) {
#pragma unroll
    for (int o = 16; o; o >>= 1) v = fmaxf(v, __shfl_xor_sync(0xffffffffu, v, o));
    return v;
}
__device__ __forceinline__ float warpred_sum(float v) {
#pragma unroll
    for (int o = 16; o; o >>= 1) v += __shfl_xor_sync(0xffffffffu, v, o);
    return v;
}

__global__ void decoder_kernel(const float* __restrict__ b_hh) {
    extern __shared__ float sm[];
    float* s_eh = sm;              // 105*132
    float* s_h = sm + 13860;
    float* s_gh = sm + 13988;
    float* s_hx2 = sm + 14372;
    float* s_att = sm + 14500;
    float* s_red = sm + 14628;
    int b = blockIdx.x, tid = threadIdx.x;

    for (int i = tid; i < 13440; i += 384) {
        int t = i >> 7, k = i & 127;
        s_eh[t * 132 + k] = g_eh[(size_t)b * 105 * 128 + i];
    }
    if (tid < 128) s_h[tid] = 0.f;
    __syncthreads();

    float bn = b_hh[tid];
    for (int l = 0; l < 63; l++) {
        float a0 = bn, a1 = 0.f;
#pragma unroll 8
        for (int k = 0; k < 64; k++) {
            a0 += g_wT[k * 384 + tid] * s_h[k];
            a1 += g_wT[(k + 64) * 384 + tid] * s_h[k + 64];
        }
        s_gh[tid] = a0 + a1;
        __syncthreads();

        if (tid < 128) {
            const float* irow = &g_ip[((size_t)b * 63 + l) * 384];
            float r = 1.f / (1.f + __expf(-(irow[tid] + s_gh[tid])));
            float z = 1.f / (1.f + __expf(-(irow[128 + tid] + s_gh[128 + tid])));
            float nn = tanhf(irow[256 + tid] + r * s_gh[256 + tid]);
            s_hx2[tid] = (1.f - z) * nn + z * s_h[tid];
        }
        __syncthreads();

        float sc = -1e30f;
        if (tid < 105) {
            const float4* er = (const float4*)&s_eh[tid * 132];
            const float4* hx = (const float4*)s_hx2;
            float d = 0.f;
#pragma unroll 8
            for (int k = 0; k < 32; k++) {
                float4 e4 = er[k], h4 = hx[k];
                d += e4.x * h4.x + e4.y * h4.y + e4.z * h4.z + e4.w * h4.w;
            }
            sc = d;
        }
        float m = warpred_max(sc);
        if ((tid & 31) == 0) s_red[tid >> 5] = m;
        __syncthreads();
        if (tid < 32) {
            float wv = (tid < 12) ? s_red[tid] : -1e30f;
            wv = warpred_max(wv);
            if (tid == 0) s_red[12] = wv;
        }
        __syncthreads();
        float mx = s_red[12];
        float e = (tid < 105) ? __expf(sc - mx) : 0.f;
        float sv = warpred_sum(e);
        if ((tid & 31) == 0) s_red[16 + (tid >> 5)] = sv;
        if (tid < 128) s_att[tid] = e;
        __syncthreads();
        if (tid < 32) {
            float wv = (tid < 12) ? s_red[16 + tid] : 0.f;
            wv = warpred_sum(wv);
            if (tid == 0) s_red[13] = wv;
        }
        __syncthreads();
        float inv = 1.f / s_red[13];

        if (tid < 128) {
            float c = 0.f;
            for (int t = 0; t < 105; t++) c += s_att[t] * s_eh[t * 132 + tid];
            c *= inv;
            s_h[tid] = c;
            g_ctxs[((size_t)b * 63 + l) * 128 + tid] = c;
        }
        __syncthreads();
    }
}

// ---------------- small helpers ----------------
__global__ void emb_gather(const int* __restrict__ y, const float* __restrict__ emb) {
    int i = blockIdx.x * 256 + threadIdx.x;
    if (i >= NB * 63 * 32) return;
    int m = i >> 5, e = i & 31;
    int bb = m / 63, l = m % 63;
    int idx = y[bb * 64 + l];
    g_embA[i] = emb[idx * 32 + e];
}

__global__ void transpose_whh(const float* __restrict__ w) {
    int i = blockIdx.x * 256 + threadIdx.x;
    if (i < 49152) {
        int n = i >> 7, k = i & 127;
        g_wT[k * 384 + n] = w[i];
    }
}

// ---------------- launch ----------------
extern "C" void kernel_launch(void* const* d_in, const int* in_sizes, int n_in,
                              void* d_out, int out_size) {
    const float* x    = (const float*)d_in[0];
    const int*   y    = (const int*)d_in[1];
    const float* mean = (const float*)d_in[2];
    const float* stdv = (const float*)d_in[3];
    const float* c1w  = (const float*)d_in[4];
    const float* c1b  = (const float*)d_in[5];
    const float* c2w  = (const float*)d_in[6];
    const float* c2b  = (const float*)d_in[7];
    const float* gwih = (const float*)d_in[8];
    const float* gwhh = (const float*)d_in[9];
    const float* gbih = (const float*)d_in[10];
    const float* gbhh = (const float*)d_in[11];
    const float* emb  = (const float*)d_in[12];
    const float* dwih = (const float*)d_in[13];
    const float* dwhh = (const float*)d_in[14];
    const float* dbih = (const float*)d_in[15];
    const float* dbhh = (const float*)d_in[16];
    const float* fcw  = (const float*)d_in[17];
    const float* fcb  = (const float*)d_in[18];
    float* out = (float*)d_out;

    cudaFuncSetAttribute(encoder_kernel, cudaFuncAttributeMaxDynamicSharedMemorySize, 204800);
    cudaFuncSetAttribute(decoder_kernel, cudaFuncAttributeMaxDynamicSharedMemorySize, 58640);
    cudaFuncSetAttribute(conv2_mma_kernel, cudaFuncAttributeMaxDynamicSharedMemorySize, 179200);

    void *p_conv2, *p_xp, *p_embA, *p_ip, *p_ctxs;
    cudaGetSymbolAddress(&p_conv2, g_conv2);
    cudaGetSymbolAddress(&p_xp, g_xp);
    cudaGetSymbolAddress(&p_embA, g_embA);
    cudaGetSymbolAddress(&p_ip, g_ip);
    cudaGetSymbolAddress(&p_ctxs, g_ctxs);

    prep_wf<<<144, 256>>>(c2w);
    transpose_whh<<<192, 256>>>(dwhh);
    conv1_kernel<<<dim3(C1H, NB), 256>>>(x, mean, stdv, c1w, c1b);
    conv2_mma_kernel<<<dim3(15, NB), 384, 179200>>>(c2b);
    // xp = conv_out @ gru_w_ih^T + gru_b_ih : (6720,1152)x(384,1152)
    gemm_nt<<<dim3(3, 53), 256>>>((const float*)p_conv2, gwih, gbih, (float*)p_xp,
                                  NB * C2H, 384, 1152);
    encoder_kernel<<<NB, 384, 204800>>>(gwhh, gbhh);

    emb_gather<<<(NB * 63 * 32 + 255) / 256, 256>>>(y, emb);
    // ip = emb_in @ dec_w_ih^T + dec_b_ih : (4032,32)x(384,32)
    gemm_nt<<<dim3(3, 32), 256>>>((const float*)p_embA, dwih, dbih, (float*)p_ip,
                                  NB * 63, 384, 32);
    decoder_kernel<<<NB, 384, 58640>>>(dbhh);
    // out = ctxs @ fc_w^T + fc_b : (4032,128)x(32,128)
    gemm_nt<<<dim3(1, 32), 256>>>((const float*)p_ctxs, fcw, fcb, out,
                                  NB * 63, 32, 128);
}

// round 14
// speedup vs baseline: 1.1703x; 1.1703x over previous
#include <cuda_runtime.h>
#include <cuda_bf16.h>
#include <math.h>
#include <stdint.h>

// Model dims: B=64,T=512,F=161,V=32,L=64,H=128,E=32
#define NB 64
#define C1H 241
#define C1W 80
#define C2H 105

typedef unsigned long long ull;

// ---------------- device scratch ----------------
__device__ __nv_bfloat16 g_c1h[NB * C1H * C1W * 32];
__device__ __nv_bfloat16 g_c1l[NB * C1H * C1W * 32];
// conv2 output as bf16 hi/lo rows [m][1152], m padded to 6784 (zero-init tail)
__device__ __nv_bfloat16 g_c2h[6784 * 1152];
__device__ __nv_bfloat16 g_c2l[6784 * 1152];
__device__ float g_xp   [NB * C2H * 384];
__device__ float g_eh   [NB * C2H * 128];
__device__ float g_embA [NB * 63 * 32];
__device__ float g_ip   [NB * 63 * 384];
__device__ float g_ctxs [NB * 63 * 128];
__device__ float g_wT   [128 * 384];
// conv2 weight B-fragments (per mma lane): (((kh*9+kw)*2+kc)*2+np)*32+lane
__device__ uint4 g_wfh[36864];
__device__ uint4 g_wfl[36864];
// xp weight B-fragments: (kstep*24 + np)*32 + lane   (72 ksteps, 24 np-groups)
__device__ uint4 g_wxh[55296];
__device__ uint4 g_wxl[55296];

// ---------------- helpers ----------------
__device__ __forceinline__ uint32_t smem_u32(const void* p) {
    uint32_t a;
    asm("{ .reg .u64 t; cvta.to.shared.u64 t, %1; cvt.u32.u64 %0, t; }" : "=r"(a) : "l"(p));
    return a;
}
__device__ __forceinline__ void ldsm4(uint32_t* d, uint32_t addr) {
    asm volatile("ldmatrix.sync.aligned.m8n8.x4.shared.b16 {%0,%1,%2,%3}, [%4];"
                 : "=r"(d[0]), "=r"(d[1]), "=r"(d[2]), "=r"(d[3]) : "r"(addr));
}
__device__ __forceinline__ void mma_bf16(float* c, const uint32_t* a,
                                         uint32_t b0, uint32_t b1) {
    asm volatile(
        "mma.sync.aligned.m16n8k16.row.col.f32.bf16.bf16.f32 "
        "{%0,%1,%2,%3}, {%4,%5,%6,%7}, {%8,%9}, {%0,%1,%2,%3};"
        : "+f"(c[0]), "+f"(c[1]), "+f"(c[2]), "+f"(c[3])
        : "r"(a[0]), "r"(a[1]), "r"(a[2]), "r"(a[3]), "r"(b0), "r"(b1));
}
__device__ __forceinline__ void cpa16(uint32_t dst, const void* src) {
    asm volatile("cp.async.cg.shared.global [%0], [%1], 16;" :: "r"(dst), "l"(src));
}
__device__ __forceinline__ uint32_t pack_bf2(float x, float y) {
    __nv_bfloat16 h0 = __float2bfloat16(x), h1 = __float2bfloat16(y);
    return ((uint32_t)__bfloat16_as_ushort(h1) << 16) | (uint32_t)__bfloat16_as_ushort(h0);
}

// ---------------- conv1: normalize + conv + relu -> bf16 hi/lo [ih][iw][ci] ----
__global__ void conv1_kernel(const float* __restrict__ x,
                             const float* __restrict__ mean,
                             const float* __restrict__ stdv,
                             const float* __restrict__ w,
                             const float* __restrict__ bias) {
    int oh = blockIdx.x, b = blockIdx.y;
    __shared__ float s_x[32 * 161];
    __shared__ float s_w[2048];
    __shared__ __nv_bfloat16 s_oh[2560], s_ol[2560];
    int tid = threadIdx.x;
    for (int i = tid; i < 32 * 161; i += 256) {
        int kh = i / 161, iw = i % 161;
        int ih = 2 * oh + kh;
        s_x[i] = (x[(b * 512 + ih) * 161 + iw] - mean[iw]) / stdv[iw];
    }
    for (int i = tid; i < 2048; i += 256) s_w[i] = w[i];
    __syncthreads();

    int c = tid >> 3, owb = tid & 7;
    float acc[10];
#pragma unroll
    for (int j = 0; j < 10; j++) acc[j] = 0.f;
    for (int kh = 0; kh < 32; kh++) {
        float w0 = s_w[c * 64 + kh * 2], w1 = s_w[c * 64 + kh * 2 + 1];
        const float* xr = &s_x[kh * 161];
#pragma unroll
        for (int j = 0; j < 10; j++) {
            int ow = owb + 8 * j;
            acc[j] += w0 * xr[2 * ow] + w1 * xr[2 * ow + 1];
        }
    }
    float bb = bias[c];
#pragma unroll
    for (int j = 0; j < 10; j++) {
        int ow = owb + 8 * j;
        float v = acc[j] + bb;
        v = v > 0.f ? v : 0.f;
        __nv_bfloat16 h = __float2bfloat16(v);
        s_oh[ow * 32 + c] = h;
        s_ol[ow * 32 + c] = __float2bfloat16(v - __bfloat162float(h));
    }
    __syncthreads();
    size_t base = (size_t)(b * C1H + oh) * 2560;
    const uint4* sh = (const uint4*)s_oh;
    const uint4* sl = (const uint4*)s_ol;
    uint4* dh = (uint4*)&g_c1h[base];
    uint4* dl = (uint4*)&g_c1l[base];
    for (int i = tid; i < 320; i += 256) { dh[i] = sh[i]; dl[i] = sl[i]; }
}

// -------- prep conv2 weight B-fragments (hi/lo) -----
__global__ void prep_wf(const float* __restrict__ w) {
    int i = blockIdx.x * 256 + threadIdx.x;
    if (i >= 36864) return;
    int lane = i & 31; int t = i >> 5;
    int np = t & 1; t >>= 1;
    int kc = t & 1; t >>= 1;
    int kw = t % 9; int kh = t / 9;
    int co0 = np * 16 + (lane >> 2);
    int ci0 = kc * 16 + 2 * (lane & 3);
    uint32_t rh[4], rl[4];
#pragma unroll
    for (int j = 0; j < 4; j++) {
        int co = co0 + (j >> 1) * 8;
        int ci = ci0 + (j & 1) * 8;
        float v0 = w[((co * 32 + ci) * 32 + kh) * 9 + kw];
        float v1 = w[((co * 32 + ci + 1) * 32 + kh) * 9 + kw];
        __nv_bfloat16 h0 = __float2bfloat16(v0), h1 = __float2bfloat16(v1);
        rh[j] = ((uint32_t)__bfloat16_as_ushort(h1) << 16)
              | (uint32_t)__bfloat16_as_ushort(h0);
        rl[j] = pack_bf2(v0 - __bfloat162float(h0), v1 - __bfloat162float(h1));
    }
    g_wfh[i] = make_uint4(rh[0], rh[1], rh[2], rh[3]);
    g_wfl[i] = make_uint4(rl[0], rl[1], rl[2], rl[3]);
}

// -------- prep xp weight B-fragments from gru_w_ih (384 x 1152) -----
__global__ void prep_wx(const float* __restrict__ w) {
    int i = blockIdx.x * 256 + threadIdx.x;
    if (i >= 55296) return;
    int lane = i & 31; int t = i >> 5;
    int np = t % 24; int ks = t / 24;
    int co0 = np * 16 + (lane >> 2);
    int k0 = ks * 16 + 2 * (lane & 3);
    uint32_t rh[4], rl[4];
#pragma unroll
    for (int j = 0; j < 4; j++) {
        int co = co0 + (j >> 1) * 8;
        int k = k0 + (j & 1) * 8;
        float v0 = w[co * 1152 + k];
        float v1 = w[co * 1152 + k + 1];
        __nv_bfloat16 h0 = __float2bfloat16(v0), h1 = __float2bfloat16(v1);
        rh[j] = ((uint32_t)__bfloat16_as_ushort(h1) << 16)
              | (uint32_t)__bfloat16_as_ushort(h0);
        rl[j] = pack_bf2(v0 - __bfloat162float(h0), v1 - __bfloat162float(h1));
    }
    g_wxh[i] = make_uint4(rh[0], rh[1], rh[2], rh[3]);
    g_wxl[i] = make_uint4(rl[0], rl[1], rl[2], rl[3]);
}

// ---------------- conv2 via mma.sync: 7-oh CTA, 2 M-tiles/warp, single buffer --
// grid (15, 64), 384 threads, 2 CTAs/SM. Epilogue writes bf16 hi/lo rows.
__global__ void __launch_bounds__(384, 2) conv2_mma_kernel(const float* __restrict__ bias) {
    extern __shared__ __align__(16) char base[];
    uint32_t sb = smem_u32(base);
    int tid = threadIdx.x, wid = tid >> 5, lane = tid & 31;
    int oh0 = blockIdx.x * 7, b = blockIdx.y;
    const __nv_bfloat16* c1h = g_c1h + (size_t)b * C1H * 2560;
    const __nv_bfloat16* c1l = g_c1l + (size_t)b * C1H * 2560;

    float acc[2][4][4];
#pragma unroll
    for (int u = 0; u < 2; u++)
#pragma unroll
        for (int i = 0; i < 4; i++)
#pragma unroll
            for (int j = 0; j < 4; j++) acc[u][i][j] = 0.f;

    int r = lane & 7, q = lane >> 3;
    uint32_t a_base[2];
#pragma unroll
    for (int u = 0; u < 2; u++) {
        int p = 16 * (wid + 8 * u) + (q & 1) * 8 + r;
        if (p > 251) p = 251;
        int pohi = p / 36, pow_ = p - 36 * pohi;
        a_base[u] = (uint32_t)((pohi * 80 + 2 * pow_) * 80) + (q >> 1) * 16;
    }

    for (int kh = 0; kh < 32; kh++) {
        int ihb = 2 * oh0 + kh;
        for (int i = tid; i < 2240; i += 384) {
            int R = i >> 2, c8 = i & 3;
            int ohi2 = R / 80, iw = R - 80 * ohi2;
            size_t src = ((size_t)(ihb + 2 * ohi2) * 80 + iw) * 32 + c8 * 8;
            uint32_t d = (uint32_t)(R * 80 + c8 * 16);
            cpa16(sb + d, c1h + src);
            cpa16(sb + 44800u + d, c1l + src);
        }
        asm volatile("cp.async.commit_group;" ::: "memory");
        asm volatile("cp.async.wait_group 0;" ::: "memory");
        __syncthreads();

        if (wid < 8) {
            const uint4* wfh = g_wfh + (size_t)kh * 1152 + lane;
            const uint4* wfl = g_wfl + (size_t)kh * 1152 + lane;
#pragma unroll 3
            for (int kw = 0; kw < 9; kw++) {
#pragma unroll
                for (int kc = 0; kc < 2; kc++) {
                    uint32_t ah[2][4], al[2][4];
#pragma unroll
                    for (int u = 0; u < 2; u++) {
                        uint32_t akw = a_base[u] + (uint32_t)kw * 80 + kc * 32;
                        ldsm4(ah[u], sb + akw);
                        ldsm4(al[u], sb + 44800u + akw);
                    }
#pragma unroll
                    for (int np = 0; np < 2; np++) {
                        int fi = ((kw * 2 + kc) * 2 + np) * 32;
                        uint4 bh = wfh[fi];
                        uint4 bl = wfl[fi];
#pragma unroll
                        for (int u = 0; u < 2; u++) {
                            mma_bf16(acc[u][2 * np],     ah[u], bh.x, bh.y);
                            mma_bf16(acc[u][2 * np + 1], ah[u], bh.z, bh.w);
                            mma_bf16(acc[u][2 * np],     ah[u], bl.x, bl.y);
                            mma_bf16(acc[u][2 * np + 1], ah[u], bl.z, bl.w);
                            mma_bf16(acc[u][2 * np],     al[u], bh.x, bh.y);
                            mma_bf16(acc[u][2 * np + 1], al[u], bh.z, bh.w);
                        }
                    }
                }
            }
        }
        __syncthreads();
    }

    // epilogue: +bias, relu, write bf16 hi/lo rows [m][co*36+ow]
    if (wid < 8) {
#pragma unroll
        for (int u = 0; u < 2; u++) {
            int row0 = 16 * (wid + 8 * u) + (lane >> 2);
#pragma unroll
            for (int nt = 0; nt < 4; nt++) {
                int col = 8 * nt + (lane & 3) * 2;
                float b0 = bias[col], b1 = bias[col + 1];
#pragma unroll
                for (int h = 0; h < 2; h++) {
                    int row = row0 + 8 * h;
                    if (row < 252) {
                        int ohi = row / 36, ow = row - 36 * ohi;
                        size_t m = (size_t)b * C2H + oh0 + ohi;
                        float v0 = acc[u][nt][2 * h] + b0;
                        float v1 = acc[u][nt][2 * h + 1] + b1;
                        v0 = v0 > 0.f ? v0 : 0.f;
                        v1 = v1 > 0.f ? v1 : 0.f;
                        __nv_bfloat16 h0 = __float2bfloat16(v0);
                        __nv_bfloat16 h1 = __float2bfloat16(v1);
                        size_t i0 = m * 1152 + col * 36 + ow;
                        g_c2h[i0] = h0;
                        g_c2l[i0] = __float2bfloat16(v0 - __bfloat162float(h0));
                        g_c2h[i0 + 36] = h1;
                        g_c2l[i0 + 36] = __float2bfloat16(v1 - __bfloat162float(h1));
                    }
                }
            }
        }
    }
}

// ---------------- xp = conv2_out @ gru_w_ih^T + b via mma -----------------------
// grid (3, 53), 256 threads (8 warps: wm=wid&3 -> 32-row tile, wn=wid>>2 -> 64 co).
// A staged per 16-k step, 48B row stride (conflict-free ldsm), double-buffered.
__global__ void __launch_bounds__(256) xp_mma_kernel(const float* __restrict__ b_ih) {
    extern __shared__ __align__(16) char base[];
    uint32_t sb = smem_u32(base);
    int tid = threadIdx.x, wid = tid >> 5, lane = tid & 31;
    int wm = wid & 3, wn = wid >> 2;
    int bm = blockIdx.y * 128;
    int npg0 = blockIdx.x * 8 + wn * 4;

    float acc[2][8][4];
#pragma unroll
    for (int mt = 0; mt < 2; mt++)
#pragma unroll
        for (int nt = 0; nt < 8; nt++)
#pragma unroll
            for (int j = 0; j < 4; j++) acc[mt][nt][j] = 0.f;

    int r = lane & 7, q = lane >> 3;
    uint32_t offA[2];
#pragma unroll
    for (int mt = 0; mt < 2; mt++) {
        int ml = wm * 32 + mt * 16 + (q & 1) * 8 + r;
        offA[mt] = (uint32_t)(ml * 48) + (q >> 1) * 16;
    }

    auto stageX = [&](int ks, int buf) {
        uint32_t bb = sb + (uint32_t)buf * 12288u;
        int k0 = ks * 16;
        for (int i = tid; i < 512; i += 256) {
            int arr = i >> 8;
            int row = (i >> 1) & 127;
            int half = i & 1;
            const __nv_bfloat16* src =
                (arr ? g_c2l : g_c2h) + (size_t)(bm + row) * 1152 + k0 + half * 8;
            cpa16(bb + (uint32_t)arr * 6144u + (uint32_t)(row * 48 + half * 16), src);
        }
        asm volatile("cp.async.commit_group;" ::: "memory");
    };

    stageX(0, 0);
    for (int ks = 0; ks < 72; ks++) {
        if (ks < 71) {
            stageX(ks + 1, (ks + 1) & 1);
            asm volatile("cp.async.wait_group 1;" ::: "memory");
        } else {
            asm volatile("cp.async.wait_group 0;" ::: "memory");
        }
        __syncthreads();

        uint32_t bb = sb + (uint32_t)(ks & 1) * 12288u;
        uint32_t ah[2][4], al[2][4];
#pragma unroll
        for (int mt = 0; mt < 2; mt++) {
            ldsm4(ah[mt], bb + offA[mt]);
            ldsm4(al[mt], bb + 6144u + offA[mt]);
        }
        const uint4* wh = g_wxh + ((size_t)ks * 24 + npg0) * 32 + lane;
        const uint4* wl = g_wxl + ((size_t)ks * 24 + npg0) * 32 + lane;
#pragma unroll
        for (int g = 0; g < 4; g++) {
            uint4 bh = wh[g * 32];
            uint4 bl = wl[g * 32];
#pragma unroll
            for (int mt = 0; mt < 2; mt++) {
                mma_bf16(acc[mt][2 * g],     ah[mt], bh.x, bh.y);
                mma_bf16(acc[mt][2 * g + 1], ah[mt], bh.z, bh.w);
                mma_bf16(acc[mt][2 * g],     ah[mt], bl.x, bl.y);
                mma_bf16(acc[mt][2 * g + 1], ah[mt], bl.z, bl.w);
                mma_bf16(acc[mt][2 * g],     al[mt], bh.x, bh.y);
                mma_bf16(acc[mt][2 * g + 1], al[mt], bh.z, bh.w);
            }
        }
        __syncthreads();
    }

    int colbase = blockIdx.x * 128 + wn * 64;
#pragma unroll
    for (int mt = 0; mt < 2; mt++) {
#pragma unroll
        for (int nt = 0; nt < 8; nt++) {
            int col = colbase + (nt >> 1) * 16 + (nt & 1) * 8 + (lane & 3) * 2;
            float b0 = b_ih[col], b1 = b_ih[col + 1];
#pragma unroll
            for (int h = 0; h < 2; h++) {
                int row = bm + wm * 32 + mt * 16 + (lane >> 2) + 8 * h;
                if (row < 6720) {
                    g_xp[(size_t)row * 384 + col]     = acc[mt][nt][2 * h] + b0;
                    g_xp[(size_t)row * 384 + col + 1] = acc[mt][nt][2 * h + 1] + b1;
                }
            }
        }
    }
}

// ---------------- generic C[M,N] = A[M,K] * B[N,K]^T + bias ----------------
__global__ void gemm_nt(const float* __restrict__ A, const float* __restrict__ Bm,
                        const float* __restrict__ bias, float* __restrict__ C,
                        int M, int N, int K) {
    __shared__ float sA[8][128];
    __shared__ float sB[8][128];
    int bm = blockIdx.y * 128, bn = blockIdx.x * 128;
    int tid = threadIdx.x;
    int ty = tid >> 4, tx = tid & 15;
    float acc[8][8];
#pragma unroll
    for (int i = 0; i < 8; i++)
#pragma unroll
        for (int j = 0; j < 8; j++) acc[i][j] = 0.f;

    int lrow = tid >> 1, lk = (tid & 1) * 4;
    for (int k0 = 0; k0 < K; k0 += 8) {
        float4 av = make_float4(0.f, 0.f, 0.f, 0.f);
        float4 bv = make_float4(0.f, 0.f, 0.f, 0.f);
        if (bm + lrow < M) av = *(const float4*)&A[(size_t)(bm + lrow) * K + k0 + lk];
        if (bn + lrow < N) bv = *(const float4*)&Bm[(size_t)(bn + lrow) * K + k0 + lk];
        sA[lk + 0][lrow] = av.x; sA[lk + 1][lrow] = av.y;
        sA[lk + 2][lrow] = av.z; sA[lk + 3][lrow] = av.w;
        sB[lk + 0][lrow] = bv.x; sB[lk + 1][lrow] = bv.y;
        sB[lk + 2][lrow] = bv.z; sB[lk + 3][lrow] = bv.w;
        __syncthreads();
#pragma unroll
        for (int k = 0; k < 8; k++) {
            float a[8], bb[8];
            *(float4*)&a[0] = *(const float4*)&sA[k][ty * 8];
            *(float4*)&a[4] = *(const float4*)&sA[k][ty * 8 + 4];
            *(float4*)&bb[0] = *(const float4*)&sB[k][tx * 8];
            *(float4*)&bb[4] = *(const float4*)&sB[k][tx * 8 + 4];
#pragma unroll
            for (int i = 0; i < 8; i++)
#pragma unroll
                for (int j = 0; j < 8; j++) acc[i][j] += a[i] * bb[j];
        }
        __syncthreads();
    }
    for (int i = 0; i < 8; i++) {
        int m = bm + ty * 8 + i;
        if (m >= M) break;
        for (int j = 0; j < 8; j++) {
            int n = bn + tx * 8 + j;
            if (n < N) C[(size_t)m * N + n] = acc[i][j] + bias[n];
        }
    }
}

// ---------------- encoder GRU: one block per batch element ----------------
__global__ void encoder_kernel(const float* __restrict__ w_hh,
                               const float* __restrict__ b_hh) {
    extern __shared__ float sm[];
    float* s_w = sm;              // 384*132 (padded stride)
    float* s_h = sm + 50688;
    float* s_gh = sm + 50816;
    int b = blockIdx.x, tid = threadIdx.x;
    for (int i = tid; i < 49152; i += 384) {
        int r = i >> 7, c = i & 127;
        s_w[r * 132 + c] = w_hh[i];
    }
    if (tid < 128) s_h[tid] = 0.f;
    __syncthreads();
    float bn = b_hh[tid];
    const float4* wr = (const float4*)&s_w[tid * 132];
    for (int t = 0; t < 105; t++) {
        float a0 = bn, a1 = 0.f;
#pragma unroll
        for (int k = 0; k < 16; k++) {
            float4 wv = wr[2 * k];
            float4 hv = ((const float4*)s_h)[2 * k];
            a0 += wv.x * hv.x + wv.y * hv.y + wv.z * hv.z + wv.w * hv.w;
            float4 wv2 = wr[2 * k + 1];
            float4 hv2 = ((const float4*)s_h)[2 * k + 1];
            a1 += wv2.x * hv2.x + wv2.y * hv2.y + wv2.z * hv2.z + wv2.w * hv2.w;
        }
        s_gh[tid] = a0 + a1;
        __syncthreads();
        if (tid < 128) {
            const float* xrow = &g_xp[((size_t)b * 105 + t) * 384];
            float r = 1.f / (1.f + __expf(-(xrow[tid] + s_gh[tid])));
            float z = 1.f / (1.f + __expf(-(xrow[128 + tid] + s_gh[128 + tid])));
            float nn = tanhf(xrow[256 + tid] + r * s_gh[256 + tid]);
            float hnew = (1.f - z) * nn + z * s_h[tid];
            s_h[tid] = hnew;
            g_eh[((size_t)b * 105 + t) * 128 + tid] = hnew;
        }
        __syncthreads();
    }
}

// ---------------- decoder: GRU step + attention, one block per batch ----------------
__device__ __forceinline__ float warpred_max(float v) {
#pragma unroll
    for (int o = 16; o; o >>= 1) v = fmaxf(v, __shfl_xor_sync(0xffffffffu, v, o));
    return v;
}
__device__ __forceinline__ float warpred_sum(float v) {
#pragma unroll
    for (int o = 16; o; o >>= 1) v += __shfl_xor_sync(0xffffffffu, v, o);
    return v;
}

__global__ void decoder_kernel(const float* __restrict__ b_hh) {
    extern __shared__ float sm[];
    float* s_eh = sm;              // 105*132
    float* s_h = sm + 13860;
    float* s_gh = sm + 13988;
    float* s_hx2 = sm + 14372;
    float* s_att = sm + 14500;
    float* s_red = sm + 14628;
    int b = blockIdx.x, tid = threadIdx.x;

    for (int i = tid; i < 13440; i += 384) {
        int t = i >> 7, k = i & 127;
        s_eh[t * 132 + k] = g_eh[(size_t)b * 105 * 128 + i];
    }
    if (tid < 128) s_h[tid] = 0.f;
    __syncthreads();

    float bn = b_hh[tid];
    for (int l = 0; l < 63; l++) {
        float a0 = bn, a1 = 0.f;
#pragma unroll 8
        for (int k = 0; k < 64; k++) {
            a0 += g_wT[k * 384 + tid] * s_h[k];
            a1 += g_wT[(k + 64) * 384 + tid] * s_h[k + 64];
        }
        s_gh[tid] = a0 + a1;
        __syncthreads();

        if (tid < 128) {
            const float* irow = &g_ip[((size_t)b * 63 + l) * 384];
            float r = 1.f / (1.f + __expf(-(irow[tid] + s_gh[tid])));
            float z = 1.f / (1.f + __expf(-(irow[128 + tid] + s_gh[128 + tid])));
            float nn = tanhf(irow[256 + tid] + r * s_gh[256 + tid]);
            s_hx2[tid] = (1.f - z) * nn + z * s_h[tid];
        }
        __syncthreads();

        float sc = -1e30f;
        if (tid < 105) {
            const float4* er = (const float4*)&s_eh[tid * 132];
            const float4* hx = (const float4*)s_hx2;
            float d = 0.f;
#pragma unroll 8
            for (int k = 0; k < 32; k++) {
                float4 e4 = er[k], h4 = hx[k];
                d += e4.x * h4.x + e4.y * h4.y + e4.z * h4.z + e4.w * h4.w;
            }
            sc = d;
        }
        float m = warpred_max(sc);
        if ((tid & 31) == 0) s_red[tid >> 5] = m;
        __syncthreads();
        if (tid < 32) {
            float wv = (tid < 12) ? s_red[tid] : -1e30f;
            wv = warpred_max(wv);
            if (tid == 0) s_red[12] = wv;
        }
        __syncthreads();
        float mx = s_red[12];
        float e = (tid < 105) ? __expf(sc - mx) : 0.f;
        float sv = warpred_sum(e);
        if ((tid & 31) == 0) s_red[16 + (tid >> 5)] = sv;
        if (tid < 128) s_att[tid] = e;
        __syncthreads();
        if (tid < 32) {
            float wv = (tid < 12) ? s_red[16 + tid] : 0.f;
            wv = warpred_sum(wv);
            if (tid == 0) s_red[13] = wv;
        }
        __syncthreads();
        float inv = 1.f / s_red[13];

        if (tid < 128) {
            float c = 0.f;
            for (int t = 0; t < 105; t++) c += s_att[t] * s_eh[t * 132 + tid];
            c *= inv;
            s_h[tid] = c;
            g_ctxs[((size_t)b * 63 + l) * 128 + tid] = c;
        }
        __syncthreads();
    }
}

// ---------------- small helpers ----------------
__global__ void emb_gather(const int* __restrict__ y, const float* __restrict__ emb) {
    int i = blockIdx.x * 256 + threadIdx.x;
    if (i >= NB * 63 * 32) return;
    int m = i >> 5, e = i & 31;
    int bb = m / 63, l = m % 63;
    int idx = y[bb * 64 + l];
    g_embA[i] = emb[idx * 32 + e];
}

__global__ void transpose_whh(const float* __restrict__ w) {
    int i = blockIdx.x * 256 + threadIdx.x;
    if (i < 49152) {
        int n = i >> 7, k = i & 127;
        g_wT[k * 384 + n] = w[i];
    }
}

// ---------------- launch ----------------
extern "C" void kernel_launch(void* const* d_in, const int* in_sizes, int n_in,
                              void* d_out, int out_size) {
    const float* x    = (const float*)d_in[0];
    const int*   y    = (const int*)d_in[1];
    const float* mean = (const float*)d_in[2];
    const float* stdv = (const float*)d_in[3];
    const float* c1w  = (const float*)d_in[4];
    const float* c1b  = (const float*)d_in[5];
    const float* c2w  = (const float*)d_in[6];
    const float* c2b  = (const float*)d_in[7];
    const float* gwih = (const float*)d_in[8];
    const float* gwhh = (const float*)d_in[9];
    const float* gbih = (const float*)d_in[10];
    const float* gbhh = (const float*)d_in[11];
    const float* emb  = (const float*)d_in[12];
    const float* dwih = (const float*)d_in[13];
    const float* dwhh = (const float*)d_in[14];
    const float* dbih = (const float*)d_in[15];
    const float* dbhh = (const float*)d_in[16];
    const float* fcw  = (const float*)d_in[17];
    const float* fcb  = (const float*)d_in[18];
    float* out = (float*)d_out;

    cudaFuncSetAttribute(encoder_kernel, cudaFuncAttributeMaxDynamicSharedMemorySize, 204800);
    cudaFuncSetAttribute(decoder_kernel, cudaFuncAttributeMaxDynamicSharedMemorySize, 58640);
    cudaFuncSetAttribute(conv2_mma_kernel, cudaFuncAttributeMaxDynamicSharedMemorySize, 89600);

    void *p_embA, *p_ctxs;
    cudaGetSymbolAddress(&p_embA, g_embA);
    cudaGetSymbolAddress(&p_ctxs, g_ctxs);
    void *p_ip;
    cudaGetSymbolAddress(&p_ip, g_ip);

    prep_wf<<<144, 256>>>(c2w);
    prep_wx<<<216, 256>>>(gwih);
    transpose_whh<<<192, 256>>>(dwhh);
    conv1_kernel<<<dim3(C1H, NB), 256>>>(x, mean, stdv, c1w, c1b);
    conv2_mma_kernel<<<dim3(15, NB), 384, 89600>>>(c2b);
    xp_mma_kernel<<<dim3(3, 53), 256, 24576>>>(gbih);
    encoder_kernel<<<NB, 384, 204800>>>(gwhh, gbhh);

    emb_gather<<<(NB * 63 * 32 + 255) / 256, 256>>>(y, emb);
    // ip = emb_in @ dec_w_ih^T + dec_b_ih : (4032,32)x(384,32)
    gemm_nt<<<dim3(3, 32), 256>>>((const float*)p_embA, dwih, dbih, (float*)p_ip,
                                  NB * 63, 384, 32);
    decoder_kernel<<<NB, 384, 58640>>>(dbhh);
    // out = ctxs @ fc_w^T + fc_b : (4032,128)x(32,128)
    gemm_nt<<<dim3(1, 32), 256>>>((const float*)p_ctxs, fcw, fcb, out,
                                  NB * 63, 32, 128);
}

// round 16
// speedup vs baseline: 1.3164x; 1.1248x over previous
#include <cuda_runtime.h>
#include <cuda_bf16.h>
#include <math.h>
#include <stdint.h>

// Model dims: B=64,T=512,F=161,V=32,L=64,H=128,E=32
#define NB 64
#define C1H 241
#define C1W 80
#define C2H 105

typedef unsigned long long ull;

// ---------------- device scratch ----------------
__device__ __nv_bfloat16 g_c1h[NB * C1H * C1W * 32];
__device__ __nv_bfloat16 g_c1l[NB * C1H * C1W * 32];
// conv2 output as bf16 hi/lo rows [m][1152], m padded to 6784 (zero-init tail)
__device__ __nv_bfloat16 g_c2h[6784 * 1152];
__device__ __nv_bfloat16 g_c2l[6784 * 1152];
__device__ float g_xp   [NB * C2H * 384];
__device__ float g_eh   [NB * C2H * 128];
__device__ float g_embA [NB * 63 * 32];
__device__ float g_ip   [NB * 63 * 384];
__device__ float g_ctxs [NB * 63 * 128];
__device__ float g_wT   [128 * 384];
// conv2 weight B-fragments (per mma lane): (((kh*9+kw)*2+kc)*2+np)*32+lane
__device__ uint4 g_wfh[36864];
__device__ uint4 g_wfl[36864];
// xp weight B-fragments: (kstep*24 + np)*32 + lane   (72 ksteps, 24 np-groups)
__device__ uint4 g_wxh[55296];
__device__ uint4 g_wxl[55296];

// ---------------- helpers ----------------
__device__ __forceinline__ uint32_t smem_u32(const void* p) {
    uint32_t a;
    asm("{ .reg .u64 t; cvta.to.shared.u64 t, %1; cvt.u32.u64 %0, t; }" : "=r"(a) : "l"(p));
    return a;
}
__device__ __forceinline__ void ldsm4(uint32_t* d, uint32_t addr) {
    asm volatile("ldmatrix.sync.aligned.m8n8.x4.shared.b16 {%0,%1,%2,%3}, [%4];"
                 : "=r"(d[0]), "=r"(d[1]), "=r"(d[2]), "=r"(d[3]) : "r"(addr));
}
__device__ __forceinline__ void mma_bf16(float* c, const uint32_t* a,
                                         uint32_t b0, uint32_t b1) {
    asm volatile(
        "mma.sync.aligned.m16n8k16.row.col.f32.bf16.bf16.f32 "
        "{%0,%1,%2,%3}, {%4,%5,%6,%7}, {%8,%9}, {%0,%1,%2,%3};"
        : "+f"(c[0]), "+f"(c[1]), "+f"(c[2]), "+f"(c[3])
        : "r"(a[0]), "r"(a[1]), "r"(a[2]), "r"(a[3]), "r"(b0), "r"(b1));
}
__device__ __forceinline__ void cpa16(uint32_t dst, const void* src) {
    asm volatile("cp.async.cg.shared.global [%0], [%1], 16;" :: "r"(dst), "l"(src));
}
__device__ __forceinline__ uint32_t pack_bf2(float x, float y) {
    __nv_bfloat16 h0 = __float2bfloat16(x), h1 = __float2bfloat16(y);
    return ((uint32_t)__bfloat16_as_ushort(h1) << 16) | (uint32_t)__bfloat16_as_ushort(h0);
}

// ---------------- conv1 v2: register-blocked, 4 oh rows per CTA ----------------
// grid (61, 64), 256 threads. Thread: ohsub=tid>>6, cg=(tid>>3)&7 (4 c), owb=tid&7
// (10 ow). Per kh: 10 x LDS.64 + 4 w LDS.64, 80 FFMA. Output: 8B 4xbf16 stores.
#define XS 162   // padded s_x row stride (floats)
__global__ void __launch_bounds__(256) conv1_kernel(const float* __restrict__ x,
                             const float* __restrict__ mean,
                             const float* __restrict__ stdv,
                             const float* __restrict__ w,
                             const float* __restrict__ bias) {
    __shared__ float s_x[38 * XS];
    __shared__ float s_w2[2048];       // [kh][c][2]
    __shared__ float s_m[161], s_i[161];
    int oh0 = blockIdx.x * 4, b = blockIdx.y;
    int tid = threadIdx.x;
    int ohsub = tid >> 6, cg = (tid >> 3) & 7, owb = tid & 7;

    for (int i = tid; i < 161; i += 256) {
        s_m[i] = mean[i];
        s_i[i] = 1.0f / stdv[i];
    }
    for (int i = tid; i < 2048; i += 256) {
        int c = i >> 6, kh = (i & 63) >> 1, t = i & 1;
        s_w2[kh * 64 + c * 2 + t] = w[i];
    }
    __syncthreads();
    for (int i = tid; i < 38 * 161; i += 256) {
        int row = i / 161, iw = i - row * 161;
        int ih = 2 * oh0 + row;
        float v = 0.f;
        if (ih < 512) v = (x[(b * 512 + ih) * 161 + iw] - s_m[iw]) * s_i[iw];
        s_x[row * XS + iw] = v;
    }
    __syncthreads();

    float acc[4][10];
#pragma unroll
    for (int cc = 0; cc < 4; cc++)
#pragma unroll
        for (int j = 0; j < 10; j++) acc[cc][j] = 0.f;

    for (int kh = 0; kh < 32; kh++) {
        const float2* xr = (const float2*)&s_x[(2 * ohsub + kh) * XS + 2 * owb];
        float2 xv[10];
#pragma unroll
        for (int j = 0; j < 10; j++) xv[j] = xr[8 * j];
        float2 wv[4];
#pragma unroll
        for (int cc = 0; cc < 4; cc++)
            wv[cc] = *(const float2*)&s_w2[kh * 64 + (cg * 4 + cc) * 2];
#pragma unroll
        for (int cc = 0; cc < 4; cc++)
#pragma unroll
            for (int j = 0; j < 10; j++)
                acc[cc][j] += wv[cc].x * xv[j].x + wv[cc].y * xv[j].y;
    }

    int oh = oh0 + ohsub;
    if (oh < C1H) {
        float bb[4];
#pragma unroll
        for (int cc = 0; cc < 4; cc++) bb[cc] = bias[cg * 4 + cc];
#pragma unroll
        for (int j = 0; j < 10; j++) {
            int ow = owb + 8 * j;
            float v[4], lo[4];
#pragma unroll
            for (int cc = 0; cc < 4; cc++) {
                float t = acc[cc][j] + bb[cc];
                t = t > 0.f ? t : 0.f;
                __nv_bfloat16 h = __float2bfloat16(t);
                v[cc] = __bfloat162float(h);
                lo[cc] = t - v[cc];
            }
            uint2 ph, pl;
            ph.x = pack_bf2(v[0], v[1]);  ph.y = pack_bf2(v[2], v[3]);
            pl.x = pack_bf2(lo[0], lo[1]); pl.y = pack_bf2(lo[2], lo[3]);
            size_t base = (((size_t)(b * C1H + oh)) * 80 + ow) * 32 + cg * 4;
            *(uint2*)&g_c1h[base] = ph;
            *(uint2*)&g_c1l[base] = pl;
        }
    }
}

// -------- prep conv2 weight B-fragments (hi/lo) -----
__global__ void prep_wf(const float* __restrict__ w) {
    int i = blockIdx.x * 256 + threadIdx.x;
    if (i >= 36864) return;
    int lane = i & 31; int t = i >> 5;
    int np = t & 1; t >>= 1;
    int kc = t & 1; t >>= 1;
    int kw = t % 9; int kh = t / 9;
    int co0 = np * 16 + (lane >> 2);
    int ci0 = kc * 16 + 2 * (lane & 3);
    uint32_t rh[4], rl[4];
#pragma unroll
    for (int j = 0; j < 4; j++) {
        int co = co0 + (j >> 1) * 8;
        int ci = ci0 + (j & 1) * 8;
        float v0 = w[((co * 32 + ci) * 32 + kh) * 9 + kw];
        float v1 = w[((co * 32 + ci + 1) * 32 + kh) * 9 + kw];
        __nv_bfloat16 h0 = __float2bfloat16(v0), h1 = __float2bfloat16(v1);
        rh[j] = ((uint32_t)__bfloat16_as_ushort(h1) << 16)
              | (uint32_t)__bfloat16_as_ushort(h0);
        rl[j] = pack_bf2(v0 - __bfloat162float(h0), v1 - __bfloat162float(h1));
    }
    g_wfh[i] = make_uint4(rh[0], rh[1], rh[2], rh[3]);
    g_wfl[i] = make_uint4(rl[0], rl[1], rl[2], rl[3]);
}

// -------- prep xp weight B-fragments from gru_w_ih (384 x 1152) -----
__global__ void prep_wx(const float* __restrict__ w) {
    int i = blockIdx.x * 256 + threadIdx.x;
    if (i >= 55296) return;
    int lane = i & 31; int t = i >> 5;
    int np = t % 24; int ks = t / 24;
    int co0 = np * 16 + (lane >> 2);
    int k0 = ks * 16 + 2 * (lane & 3);
    uint32_t rh[4], rl[4];
#pragma unroll
    for (int j = 0; j < 4; j++) {
        int co = co0 + (j >> 1) * 8;
        int k = k0 + (j & 1) * 8;
        float v0 = w[co * 1152 + k];
        float v1 = w[co * 1152 + k + 1];
        __nv_bfloat16 h0 = __float2bfloat16(v0), h1 = __float2bfloat16(v1);
        rh[j] = ((uint32_t)__bfloat16_as_ushort(h1) << 16)
              | (uint32_t)__bfloat16_as_ushort(h0);
        rl[j] = pack_bf2(v0 - __bfloat162float(h0), v1 - __bfloat162float(h1));
    }
    g_wxh[i] = make_uint4(rh[0], rh[1], rh[2], rh[3]);
    g_wxl[i] = make_uint4(rl[0], rl[1], rl[2], rl[3]);
}

// ---------------- conv2 via mma.sync: 7-oh CTA, 2 M-tiles/warp, single buffer --
// grid (15, 64), 384 threads, 2 CTAs/SM. Epilogue writes bf16 hi/lo rows.
__global__ void __launch_bounds__(384, 2) conv2_mma_kernel(const float* __restrict__ bias) {
    extern __shared__ __align__(16) char base[];
    uint32_t sb = smem_u32(base);
    int tid = threadIdx.x, wid = tid >> 5, lane = tid & 31;
    int oh0 = blockIdx.x * 7, b = blockIdx.y;
    const __nv_bfloat16* c1h = g_c1h + (size_t)b * C1H * 2560;
    const __nv_bfloat16* c1l = g_c1l + (size_t)b * C1H * 2560;

    float acc[2][4][4];
#pragma unroll
    for (int u = 0; u < 2; u++)
#pragma unroll
        for (int i = 0; i < 4; i++)
#pragma unroll
            for (int j = 0; j < 4; j++) acc[u][i][j] = 0.f;

    int r = lane & 7, q = lane >> 3;
    uint32_t a_base[2];
#pragma unroll
    for (int u = 0; u < 2; u++) {
        int p = 16 * (wid + 8 * u) + (q & 1) * 8 + r;
        if (p > 251) p = 251;
        int pohi = p / 36, pow_ = p - 36 * pohi;
        a_base[u] = (uint32_t)((pohi * 80 + 2 * pow_) * 80) + (q >> 1) * 16;
    }

    for (int kh = 0; kh < 32; kh++) {
        int ihb = 2 * oh0 + kh;
        for (int i = tid; i < 2240; i += 384) {
            int R = i >> 2, c8 = i & 3;
            int ohi2 = R / 80, iw = R - 80 * ohi2;
            size_t src = ((size_t)(ihb + 2 * ohi2) * 80 + iw) * 32 + c8 * 8;
            uint32_t d = (uint32_t)(R * 80 + c8 * 16);
            cpa16(sb + d, c1h + src);
            cpa16(sb + 44800u + d, c1l + src);
        }
        asm volatile("cp.async.commit_group;" ::: "memory");
        asm volatile("cp.async.wait_group 0;" ::: "memory");
        __syncthreads();

        if (wid < 8) {
            const uint4* wfh = g_wfh + (size_t)kh * 1152 + lane;
            const uint4* wfl = g_wfl + (size_t)kh * 1152 + lane;
#pragma unroll 3
            for (int kw = 0; kw < 9; kw++) {
#pragma unroll
                for (int kc = 0; kc < 2; kc++) {
                    uint32_t ah[2][4], al[2][4];
#pragma unroll
                    for (int u = 0; u < 2; u++) {
                        uint32_t akw = a_base[u] + (uint32_t)kw * 80 + kc * 32;
                        ldsm4(ah[u], sb + akw);
                        ldsm4(al[u], sb + 44800u + akw);
                    }
#pragma unroll
                    for (int np = 0; np < 2; np++) {
                        int fi = ((kw * 2 + kc) * 2 + np) * 32;
                        uint4 bh = wfh[fi];
                        uint4 bl = wfl[fi];
#pragma unroll
                        for (int u = 0; u < 2; u++) {
                            mma_bf16(acc[u][2 * np],     ah[u], bh.x, bh.y);
                            mma_bf16(acc[u][2 * np + 1], ah[u], bh.z, bh.w);
                            mma_bf16(acc[u][2 * np],     ah[u], bl.x, bl.y);
                            mma_bf16(acc[u][2 * np + 1], ah[u], bl.z, bl.w);
                            mma_bf16(acc[u][2 * np],     al[u], bh.x, bh.y);
                            mma_bf16(acc[u][2 * np + 1], al[u], bh.z, bh.w);
                        }
                    }
                }
            }
        }
        __syncthreads();
    }

    // epilogue: +bias, relu, write bf16 hi/lo rows [m][co*36+ow]
    if (wid < 8) {
#pragma unroll
        for (int u = 0; u < 2; u++) {
            int row0 = 16 * (wid + 8 * u) + (lane >> 2);
#pragma unroll
            for (int nt = 0; nt < 4; nt++) {
                int col = 8 * nt + (lane & 3) * 2;
                float b0 = bias[col], b1 = bias[col + 1];
#pragma unroll
                for (int h = 0; h < 2; h++) {
                    int row = row0 + 8 * h;
                    if (row < 252) {
                        int ohi = row / 36, ow = row - 36 * ohi;
                        size_t m = (size_t)b * C2H + oh0 + ohi;
                        float v0 = acc[u][nt][2 * h] + b0;
                        float v1 = acc[u][nt][2 * h + 1] + b1;
                        v0 = v0 > 0.f ? v0 : 0.f;
                        v1 = v1 > 0.f ? v1 : 0.f;
                        __nv_bfloat16 h0 = __float2bfloat16(v0);
                        __nv_bfloat16 h1 = __float2bfloat16(v1);
                        size_t i0 = m * 1152 + col * 36 + ow;
                        g_c2h[i0] = h0;
                        g_c2l[i0] = __float2bfloat16(v0 - __bfloat162float(h0));
                        g_c2h[i0 + 36] = h1;
                        g_c2l[i0 + 36] = __float2bfloat16(v1 - __bfloat162float(h1));
                    }
                }
            }
        }
    }
}

// ---------------- xp = conv2_out @ gru_w_ih^T + b via mma -----------------------
__global__ void __launch_bounds__(256) xp_mma_kernel(const float* __restrict__ b_ih) {
    extern __shared__ __align__(16) char base[];
    uint32_t sb = smem_u32(base);
    int tid = threadIdx.x, wid = tid >> 5, lane = tid & 31;
    int wm = wid & 3, wn = wid >> 2;
    int bm = blockIdx.y * 128;
    int npg0 = blockIdx.x * 8 + wn * 4;

    float acc[2][8][4];
#pragma unroll
    for (int mt = 0; mt < 2; mt++)
#pragma unroll
        for (int nt = 0; nt < 8; nt++)
#pragma unroll
            for (int j = 0; j < 4; j++) acc[mt][nt][j] = 0.f;

    int r = lane & 7, q = lane >> 3;
    uint32_t offA[2];
#pragma unroll
    for (int mt = 0; mt < 2; mt++) {
        int ml = wm * 32 + mt * 16 + (q & 1) * 8 + r;
        offA[mt] = (uint32_t)(ml * 48) + (q >> 1) * 16;
    }

    auto stageX = [&](int ks, int buf) {
        uint32_t bb = sb + (uint32_t)buf * 12288u;
        int k0 = ks * 16;
        for (int i = tid; i < 512; i += 256) {
            int arr = i >> 8;
            int row = (i >> 1) & 127;
            int half = i & 1;
            const __nv_bfloat16* src =
                (arr ? g_c2l : g_c2h) + (size_t)(bm + row) * 1152 + k0 + half * 8;
            cpa16(bb + (uint32_t)arr * 6144u + (uint32_t)(row * 48 + half * 16), src);
        }
        asm volatile("cp.async.commit_group;" ::: "memory");
    };

    stageX(0, 0);
    for (int ks = 0; ks < 72; ks++) {
        if (ks < 71) {
            stageX(ks + 1, (ks + 1) & 1);
            asm volatile("cp.async.wait_group 1;" ::: "memory");
        } else {
            asm volatile("cp.async.wait_group 0;" ::: "memory");
        }
        __syncthreads();

        uint32_t bb = sb + (uint32_t)(ks & 1) * 12288u;
        uint32_t ah[2][4], al[2][4];
#pragma unroll
        for (int mt = 0; mt < 2; mt++) {
            ldsm4(ah[mt], bb + offA[mt]);
            ldsm4(al[mt], bb + 6144u + offA[mt]);
        }
        const uint4* wh = g_wxh + ((size_t)ks * 24 + npg0) * 32 + lane;
        const uint4* wl = g_wxl + ((size_t)ks * 24 + npg0) * 32 + lane;
#pragma unroll
        for (int g = 0; g < 4; g++) {
            uint4 bh = wh[g * 32];
            uint4 bl = wl[g * 32];
#pragma unroll
            for (int mt = 0; mt < 2; mt++) {
                mma_bf16(acc[mt][2 * g],     ah[mt], bh.x, bh.y);
                mma_bf16(acc[mt][2 * g + 1], ah[mt], bh.z, bh.w);
                mma_bf16(acc[mt][2 * g],     ah[mt], bl.x, bl.y);
                mma_bf16(acc[mt][2 * g + 1], ah[mt], bl.z, bl.w);
                mma_bf16(acc[mt][2 * g],     al[mt], bh.x, bh.y);
                mma_bf16(acc[mt][2 * g + 1], al[mt], bh.z, bh.w);
            }
        }
        __syncthreads();
    }

    int colbase = blockIdx.x * 128 + wn * 64;
#pragma unroll
    for (int mt = 0; mt < 2; mt++) {
#pragma unroll
        for (int nt = 0; nt < 8; nt++) {
            int col = colbase + (nt >> 1) * 16 + (nt & 1) * 8 + (lane & 3) * 2;
            float b0 = b_ih[col], b1 = b_ih[col + 1];
#pragma unroll
            for (int h = 0; h < 2; h++) {
                int row = bm + wm * 32 + mt * 16 + (lane >> 2) + 8 * h;
                if (row < 6720) {
                    g_xp[(size_t)row * 384 + col]     = acc[mt][nt][2 * h] + b0;
                    g_xp[(size_t)row * 384 + col + 1] = acc[mt][nt][2 * h + 1] + b1;
                }
            }
        }
    }
}

// ---------------- generic C[M,N] = A[M,K] * B[N,K]^T + bias ----------------
__global__ void gemm_nt(const float* __restrict__ A, const float* __restrict__ Bm,
                        const float* __restrict__ bias, float* __restrict__ C,
                        int M, int N, int K) {
    __shared__ float sA[8][128];
    __shared__ float sB[8][128];
    int bm = blockIdx.y * 128, bn = blockIdx.x * 128;
    int tid = threadIdx.x;
    int ty = tid >> 4, tx = tid & 15;
    float acc[8][8];
#pragma unroll
    for (int i = 0; i < 8; i++)
#pragma unroll
        for (int j = 0; j < 8; j++) acc[i][j] = 0.f;

    int lrow = tid >> 1, lk = (tid & 1) * 4;
    for (int k0 = 0; k0 < K; k0 += 8) {
        float4 av = make_float4(0.f, 0.f, 0.f, 0.f);
        float4 bv = make_float4(0.f, 0.f, 0.f, 0.f);
        if (bm + lrow < M) av = *(const float4*)&A[(size_t)(bm + lrow) * K + k0 + lk];
        if (bn + lrow < N) bv = *(const float4*)&Bm[(size_t)(bn + lrow) * K + k0 + lk];
        sA[lk + 0][lrow] = av.x; sA[lk + 1][lrow] = av.y;
        sA[lk + 2][lrow] = av.z; sA[lk + 3][lrow] = av.w;
        sB[lk + 0][lrow] = bv.x; sB[lk + 1][lrow] = bv.y;
        sB[lk + 2][lrow] = bv.z; sB[lk + 3][lrow] = bv.w;
        __syncthreads();
#pragma unroll
        for (int k = 0; k < 8; k++) {
            float a[8], bb[8];
            *(float4*)&a[0] = *(const float4*)&sA[k][ty * 8];
            *(float4*)&a[4] = *(const float4*)&sA[k][ty * 8 + 4];
            *(float4*)&bb[0] = *(const float4*)&sB[k][tx * 8];
            *(float4*)&bb[4] = *(const float4*)&sB[k][tx * 8 + 4];
#pragma unroll
            for (int i = 0; i < 8; i++)
#pragma unroll
                for (int j = 0; j < 8; j++) acc[i][j] += a[i] * bb[j];
        }
        __syncthreads();
    }
    for (int i = 0; i < 8; i++) {
        int m = bm + ty * 8 + i;
        if (m >= M) break;
        for (int j = 0; j < 8; j++) {
            int n = bn + tx * 8 + j;
            if (n < N) C[(size_t)m * N + n] = acc[i][j] + bias[n];
        }
    }
}

// ---------------- encoder GRU: one block per batch element ----------------
__global__ void encoder_kernel(const float* __restrict__ w_hh,
                               const float* __restrict__ b_hh) {
    extern __shared__ float sm[];
    float* s_w = sm;              // 384*132 (padded stride)
    float* s_h = sm + 50688;
    float* s_gh = sm + 50816;
    int b = blockIdx.x, tid = threadIdx.x;
    for (int i = tid; i < 49152; i += 384) {
        int r = i >> 7, c = i & 127;
        s_w[r * 132 + c] = w_hh[i];
    }
    if (tid < 128) s_h[tid] = 0.f;
    __syncthreads();
    float bn = b_hh[tid];
    const float4* wr = (const float4*)&s_w[tid * 132];
    for (int t = 0; t < 105; t++) {
        float a0 = bn, a1 = 0.f;
#pragma unroll
        for (int k = 0; k < 16; k++) {
            float4 wv = wr[2 * k];
            float4 hv = ((const float4*)s_h)[2 * k];
            a0 += wv.x * hv.x + wv.y * hv.y + wv.z * hv.z + wv.w * hv.w;
            float4 wv2 = wr[2 * k + 1];
            float4 hv2 = ((const float4*)s_h)[2 * k + 1];
            a1 += wv2.x * hv2.x + wv2.y * hv2.y + wv2.z * hv2.z + wv2.w * hv2.w;
        }
        s_gh[tid] = a0 + a1;
        __syncthreads();
        if (tid < 128) {
            const float* xrow = &g_xp[((size_t)b * 105 + t) * 384];
            float r = 1.f / (1.f + __expf(-(xrow[tid] + s_gh[tid])));
            float z = 1.f / (1.f + __expf(-(xrow[128 + tid] + s_gh[128 + tid])));
            float nn = tanhf(xrow[256 + tid] + r * s_gh[256 + tid]);
            float hnew = (1.f - z) * nn + z * s_h[tid];
            s_h[tid] = hnew;
            g_eh[((size_t)b * 105 + t) * 128 + tid] = hnew;
        }
        __syncthreads();
    }
}

// ---------------- decoder: GRU step + attention, one block per batch ----------------
__device__ __forceinline__ float warpred_max(float v) {
#pragma unroll
    for (int o = 16; o; o >>= 1) v = fmaxf(v, __shfl_xor_sync(0xffffffffu, v, o));
    return v;
}
__device__ __forceinline__ float warpred_sum(float v) {
#pragma unroll
    for (int o = 16; o; o >>= 1) v += __shfl_xor_sync(0xffffffffu, v, o);
    return v;
}

__global__ void decoder_kernel(const float* __restrict__ b_hh) {
    extern __shared__ float sm[];
    float* s_eh = sm;              // 105*132
    float* s_h = sm + 13860;
    float* s_gh = sm + 13988;
    float* s_hx2 = sm + 14372;
    float* s_att = sm + 14500;
    float* s_red = sm + 14628;
    int b = blockIdx.x, tid = threadIdx.x;

    for (int i = tid; i < 13440; i += 384) {
        int t = i >> 7, k = i & 127;
        s_eh[t * 132 + k] = g_eh[(size_t)b * 105 * 128 + i];
    }
    if (tid < 128) s_h[tid] = 0.f;
    __syncthreads();

    float bn = b_hh[tid];
    for (int l = 0; l < 63; l++) {
        float a0 = bn, a1 = 0.f;
#pragma unroll 8
        for (int k = 0; k < 64; k++) {
            a0 += g_wT[k * 384 + tid] * s_h[k];
            a1 += g_wT[(k + 64) * 384 + tid] * s_h[k + 64];
        }
        s_gh[tid] = a0 + a1;
        __syncthreads();

        if (tid < 128) {
            const float* irow = &g_ip[((size_t)b * 63 + l) * 384];
            float r = 1.f / (1.f + __expf(-(irow[tid] + s_gh[tid])));
            float z = 1.f / (1.f + __expf(-(irow[128 + tid] + s_gh[128 + tid])));
            float nn = tanhf(irow[256 + tid] + r * s_gh[256 + tid]);
            s_hx2[tid] = (1.f - z) * nn + z * s_h[tid];
        }
        __syncthreads();

        float sc = -1e30f;
        if (tid < 105) {
            const float4* er = (const float4*)&s_eh[tid * 132];
            const float4* hx = (const float4*)s_hx2;
            float d = 0.f;
#pragma unroll 8
            for (int k = 0; k < 32; k++) {
                float4 e4 = er[k], h4 = hx[k];
                d += e4.x * h4.x + e4.y * h4.y + e4.z * h4.z + e4.w * h4.w;
            }
            sc = d;
        }
        float m = warpred_max(sc);
        if ((tid & 31) == 0) s_red[tid >> 5] = m;
        __syncthreads();
        if (tid < 32) {
            float wv = (tid < 12) ? s_red[tid] : -1e30f;
            wv = warpred_max(wv);
            if (tid == 0) s_red[12] = wv;
        }
        __syncthreads();
        float mx = s_red[12];
        float e = (tid < 105) ? __expf(sc - mx) : 0.f;
        float sv = warpred_sum(e);
        if ((tid & 31) == 0) s_red[16 + (tid >> 5)] = sv;
        if (tid < 128) s_att[tid] = e;
        __syncthreads();
        if (tid < 32) {
            float wv = (tid < 12) ? s_red[16 + tid] : 0.f;
            wv = warpred_sum(wv);
            if (tid == 0) s_red[13] = wv;
        }
        __syncthreads();
        float inv = 1.f / s_red[13];

        if (tid < 128) {
            float c = 0.f;
            for (int t = 0; t < 105; t++) c += s_att[t] * s_eh[t * 132 + tid];
            c *= inv;
            s_h[tid] = c;
            g_ctxs[((size_t)b * 63 + l) * 128 + tid] = c;
        }
        __syncthreads();
    }
}

// ---------------- small helpers ----------------
__global__ void emb_gather(const int* __restrict__ y, const float* __restrict__ emb) {
    int i = blockIdx.x * 256 + threadIdx.x;
    if (i >= NB * 63 * 32) return;
    int m = i >> 5, e = i & 31;
    int bb = m / 63, l = m % 63;
    int idx = y[bb * 64 + l];
    g_embA[i] = emb[idx * 32 + e];
}

__global__ void transpose_whh(const float* __restrict__ w) {
    int i = blockIdx.x * 256 + threadIdx.x;
    if (i < 49152) {
        int n = i >> 7, k = i & 127;
        g_wT[k * 384 + n] = w[i];
    }
}

// ---------------- launch ----------------
extern "C" void kernel_launch(void* const* d_in, const int* in_sizes, int n_in,
                              void* d_out, int out_size) {
    const float* x    = (const float*)d_in[0];
    const int*   y    = (const int*)d_in[1];
    const float* mean = (const float*)d_in[2];
    const float* stdv = (const float*)d_in[3];
    const float* c1w  = (const float*)d_in[4];
    const float* c1b  = (const float*)d_in[5];
    const float* c2w  = (const float*)d_in[6];
    const float* c2b  = (const float*)d_in[7];
    const float* gwih = (const float*)d_in[8];
    const float* gwhh = (const float*)d_in[9];
    const float* gbih = (const float*)d_in[10];
    const float* gbhh = (const float*)d_in[11];
    const float* emb  = (const float*)d_in[12];
    const float* dwih = (const float*)d_in[13];
    const float* dwhh = (const float*)d_in[14];
    const float* dbih = (const float*)d_in[15];
    const float* dbhh = (const float*)d_in[16];
    const float* fcw  = (const float*)d_in[17];
    const float* fcb  = (const float*)d_in[18];
    float* out = (float*)d_out;

    cudaFuncSetAttribute(encoder_kernel, cudaFuncAttributeMaxDynamicSharedMemorySize, 204800);
    cudaFuncSetAttribute(decoder_kernel, cudaFuncAttributeMaxDynamicSharedMemorySize, 58640);
    cudaFuncSetAttribute(conv2_mma_kernel, cudaFuncAttributeMaxDynamicSharedMemorySize, 89600);

    void *p_embA, *p_ctxs, *p_ip;
    cudaGetSymbolAddress(&p_embA, g_embA);
    cudaGetSymbolAddress(&p_ctxs, g_ctxs);
    cudaGetSymbolAddress(&p_ip, g_ip);

    prep_wf<<<144, 256>>>(c2w);
    prep_wx<<<216, 256>>>(gwih);
    transpose_whh<<<192, 256>>>(dwhh);
    conv1_kernel<<<dim3(61, NB), 256>>>(x, mean, stdv, c1w, c1b);
    conv2_mma_kernel<<<dim3(15, NB), 384, 89600>>>(c2b);
    xp_mma_kernel<<<dim3(3, 53), 256, 24576>>>(gbih);
    encoder_kernel<<<NB, 384, 204800>>>(gwhh, gbhh);

    emb_gather<<<(NB * 63 * 32 + 255) / 256, 256>>>(y, emb);
    // ip = emb_in @ dec_w_ih^T + dec_b_ih : (4032,32)x(384,32)
    gemm_nt<<<dim3(3, 32), 256>>>((const float*)p_embA, dwih, dbih, (float*)p_ip,
                                  NB * 63, 384, 32);
    decoder_kernel<<<NB, 384, 58640>>>(dbhh);
    // out = ctxs @ fc_w^T + fc_b : (4032,128)x(32,128)
    gemm_nt<<<dim3(1, 32), 256>>>((const float*)p_ctxs, fcw, fcb, out,
                                  NB * 63, 32, 128);
}